// round 5
// baseline (speedup 1.0000x reference)
#include <cuda_runtime.h>
#include <cmath>

#define B 64
#define C 32
#define HW 16
#define IMG (C*HW*HW)        // 8192
#define TOT (B*IMG)          // 524288
#define NE 4096
#define NIDX 21824
#define ROWLEN 341
#define TCODES 128

// ---------------- scratch (no allocations allowed) ----------------
__device__ float g_zres[TOT];
__device__ float g_zhat[TOT];
__device__ float g_r[TOT];            // max N*C = 16384*32
__device__ float g_qup[TOT];
__device__ float g_hesq[NE];          // 0.5*||e||^2
__device__ unsigned long long g_res64[16384];
__device__ int   g_idx[NIDX];
__device__ float g_losspart[5*256];
__device__ int   g_itab[4][16][4];
__device__ float g_wtab[4][16][4];

// ---------------- helpers ----------------
__device__ __forceinline__ float cubicw(float x){
    const float A = -0.75f;
    x = fabsf(x);
    if (x <= 1.f) return ((A + 2.f)*x - (A + 3.f))*x*x + 1.f;
    if (x < 2.f)  return A*(((x - 5.f)*x + 8.f)*x - 4.f);
    return 0.f;
}
// order-preserving float -> uint map
__device__ __forceinline__ unsigned ford(float f){
    unsigned u = __float_as_uint(f);
    return (u & 0x80000000u) ? ~u : (u | 0x80000000u);
}

// ---------------- setup: copy z_res, zero z_hat, 0.5||e||^2, bicubic tables ----------------
__global__ void setup_kernel(const float* __restrict__ z, const float* __restrict__ emb){
    int t = blockIdx.x*blockDim.x + threadIdx.x;
    if (t < TOT){ g_zres[t] = z[t]; g_zhat[t] = 0.f; }
    if (t < NE){
        float s = 0.f;
        #pragma unroll
        for (int k = 0; k < C; k++){ float e = emb[t*C + k]; s += e*e; }
        g_hesq[t] = 0.5f*s;
    }
    if (t < 256){
        int s = t >> 6, rem = t & 63, Y = rem >> 2, a = rem & 3;
        int ph = 1 << s;
        float scale = (float)ph / 16.f;
        float src = ((float)Y + 0.5f)*scale - 0.5f;
        float i0 = floorf(src);
        float fr = src - i0;
        int off = a - 1;
        int idx = (int)i0 + off;
        idx = min(max(idx, 0), ph - 1);
        g_itab[s][Y][a] = idx;
        g_wtab[s][Y][a] = cubicw(fr - (float)off);
    }
}

// ---------------- area pool to [N][C] channel-last ----------------
__global__ void pool_kernel(int ph){
    int t = blockIdx.x*blockDim.x + threadIdx.x;
    int N = B*ph*ph;
    if (t >= N*C) return;
    int n = t >> 5, c = t & 31;
    int pp = ph*ph;
    int b = n / pp, rem = n % pp, y = rem / ph, x = rem % ph;
    int f = HW / ph;
    const float* base = g_zres + ((b*C + c)*HW + y*f)*HW + x*f;
    float s = 0.f;
    for (int dy = 0; dy < f; dy++)
        for (int dx = 0; dx < f; dx++)
            s += base[dy*HW + dx];
    g_r[n*C + c] = s * (1.f / (float)(f*f));
    if (c == 0) g_res64[n] = 0xFFFFFFFFFFFFFFFFull;
}

// ---------------- code search: score = 0.5||e||^2 - r.e (scalar FFMA, SMEM broadcast) ----------------
__global__ __launch_bounds__(128) void argmin_kernel(const float* __restrict__ emb, int N, int chunk){
    __shared__ __align__(16) float et[TCODES*C];   // [code][dim], natural layout
    __shared__ float hs[TCODES];
    int tid = threadIdx.x;
    int row = blockIdx.x*128 + tid;
    int cbase = blockIdx.y * chunk;
    bool active = row < N;

    float r[C];
    if (active){
        const float4* rp = (const float4*)(g_r + row*C);
        #pragma unroll
        for (int k = 0; k < 8; k++){
            float4 v = rp[k];
            r[4*k+0] = v.x; r[4*k+1] = v.y; r[4*k+2] = v.z; r[4*k+3] = v.w;
        }
    }
    float best = 3.4e38f; int bcode = 0;

    for (int tb = 0; tb < chunk; tb += TCODES){
        int code = cbase + tb + tid;
        const float4* src = (const float4*)(emb + code*C);
        float4* dst = (float4*)(et + tid*C);
        __syncthreads();   // prior tile fully consumed
        #pragma unroll
        for (int k = 0; k < 8; k++) dst[k] = src[k];
        hs[tid] = g_hesq[code];
        __syncthreads();
        if (active){
            for (int j = 0; j < TCODES; j += 4){
                const float4* e0 = (const float4*)(et + (j+0)*C);
                const float4* e1 = (const float4*)(et + (j+1)*C);
                const float4* e2 = (const float4*)(et + (j+2)*C);
                const float4* e3 = (const float4*)(et + (j+3)*C);
                float d0 = 0.f, d1 = 0.f, d2 = 0.f, d3 = 0.f;
                #pragma unroll
                for (int k = 0; k < 8; k++){
                    float4 a = e0[k], bb = e1[k], cc4 = e2[k], dd = e3[k];
                    d0 += r[4*k+0]*a.x;   d0 += r[4*k+1]*a.y;   d0 += r[4*k+2]*a.z;   d0 += r[4*k+3]*a.w;
                    d1 += r[4*k+0]*bb.x;  d1 += r[4*k+1]*bb.y;  d1 += r[4*k+2]*bb.z;  d1 += r[4*k+3]*bb.w;
                    d2 += r[4*k+0]*cc4.x; d2 += r[4*k+1]*cc4.y; d2 += r[4*k+2]*cc4.z; d2 += r[4*k+3]*cc4.w;
                    d3 += r[4*k+0]*dd.x;  d3 += r[4*k+1]*dd.y;  d3 += r[4*k+2]*dd.z;  d3 += r[4*k+3]*dd.w;
                }
                float s0 = hs[j+0] - d0;
                float s1 = hs[j+1] - d1;
                float s2 = hs[j+2] - d2;
                float s3 = hs[j+3] - d3;
                int c0 = cbase + tb + j;
                if (s0 < best){ best = s0; bcode = c0 + 0; }
                if (s1 < best){ best = s1; bcode = c0 + 1; }
                if (s2 < best){ best = s2; bcode = c0 + 2; }
                if (s3 < best){ best = s3; bcode = c0 + 3; }
            }
        }
    }
    if (active){
        unsigned long long key = ((unsigned long long)ford(best) << 32) | (unsigned)bcode;
        atomicMin(&g_res64[row], key);
    }
}

// ---------------- gather + bicubic upsample to q_up [B][C][16][16], extract idx ----------------
__global__ void gather_kernel(const float* __restrict__ emb, int si, int ph, int idx_ofs){
    int t = blockIdx.x*blockDim.x + threadIdx.x;
    if (t >= TOT) return;
    int N = B*ph*ph;
    if (t < N) g_idx[idx_ofs + t] = (int)(g_res64[t] & 0xFFFFFFFFull);

    int x = t & 15, y = (t >> 4) & 15, c = (t >> 8) & 31, b = t >> 13;
    float out;
    if (si == 4){
        int n = (b*16 + y)*16 + x;
        int code = (int)(g_res64[n] & 0xFFFFFFFFull);
        out = emb[code*C + c];
    } else {
        int pp = ph*ph;
        float acc = 0.f;
        #pragma unroll
        for (int ax = 0; ax < 4; ax++){
            int   ix = g_itab[si][x][ax];
            float wx = g_wtab[si][x][ax];
            float sy = 0.f;
            #pragma unroll
            for (int ay = 0; ay < 4; ay++){
                int   iy = g_itab[si][y][ay];
                float wy = g_wtab[si][y][ay];
                int n = b*pp + iy*ph + ix;
                int code = (int)(g_res64[n] & 0xFFFFFFFFull);
                sy += wy * emb[code*C + c];
            }
            acc += wx * sy;
        }
        out = acc;
    }
    g_qup[t] = out;
}

// ---------------- Phi conv3x3 + residual update + loss partials ----------------
__global__ __launch_bounds__(128) void conv_update_kernel(const float* __restrict__ z,
        const float* __restrict__ w, const float* __restrict__ bias, int si){
    __shared__ float s_in[C][HW][HW];   // 32 KB
    __shared__ float s_w[8*C*9];        // 9 KB
    __shared__ float red[128];
    int b = blockIdx.x, og = blockIdx.y, t = threadIdx.x;

    const float4* gsrc = (const float4*)(g_qup + b*IMG);
    float4* sdst = (float4*)&s_in[0][0][0];
    for (int i = t; i < IMG/4; i += 128) sdst[i] = gsrc[i];
    for (int i = t; i < 8*C*9; i += 128) s_w[i] = w[og*8*C*9 + i];
    __syncthreads();

    int oc_l = t >> 4;   // 0..7
    int x    = t & 15;   // lanes vary over x -> conflict-free SMEM
    float acc[HW];
    #pragma unroll
    for (int y = 0; y < HW; y++) acc[y] = 0.f;

    for (int ci = 0; ci < C; ci++){
        #pragma unroll
        for (int kx = 0; kx < 3; kx++){
            int xx = x + kx - 1;
            if (xx < 0 || xx >= HW) continue;   // zero pad
            float w0 = s_w[(oc_l*C + ci)*9 + 0*3 + kx];
            float w1 = s_w[(oc_l*C + ci)*9 + 1*3 + kx];
            float w2 = s_w[(oc_l*C + ci)*9 + 2*3 + kx];
            #pragma unroll
            for (int yy = 0; yy < HW; yy++){
                float v = s_in[ci][yy][xx];
                if (yy >= 1)      acc[yy-1] += w2 * v;  // ky=2 -> y = yy-1
                acc[yy] += w1 * v;                      // ky=1 -> y = yy
                if (yy+1 < HW)    acc[yy+1] += w0 * v;  // ky=0 -> y = yy+1
            }
        }
    }

    int oc = og*8 + oc_l;
    float bval = bias[oc];
    float ls = 0.f;
    int gbase = ((b*C + oc)*HW)*HW + x;
    #pragma unroll
    for (int y = 0; y < HW; y++){
        float qv = 0.5f*s_in[oc][y][x] + 0.5f*(acc[y] + bval);
        int g = gbase + y*HW;
        float zh = g_zhat[g] + qv;
        g_zhat[g] = zh;
        g_zres[g] -= qv;
        float d = zh - z[g];
        ls += d*d;
    }
    red[t] = ls;
    __syncthreads();
    for (int s = 64; s > 0; s >>= 1){
        if (t < s) red[t] += red[t+s];
        __syncthreads();
    }
    if (t == 0) g_losspart[si*256 + b*4 + og] = red[0];
}

// ---------------- final pack: z_hat_st, loss, idx (as float values, batch-major scale blocks) ----------------
__global__ void pack_kernel(const float* __restrict__ z, float* __restrict__ out){
    int t = blockIdx.x*blockDim.x + threadIdx.x;
    if (t < TOT) out[t] = (g_zhat[t] - z[t]) + z[t];   // straight-through: value == z_hat
    if (t == 0){
        float s = 0.f;
        for (int i = 0; i < 5*256; i++) s += g_losspart[i];
        out[TOT] = s * (1.25f / ((float)TOT * 5.f));
    }
    if (t < NIDX){
        int base, pp, ofs_row;
        if      (t <   64){ base=0;    pp=1;   ofs_row=0;  }
        else if (t <  320){ base=64;   pp=4;   ofs_row=1;  }
        else if (t < 1344){ base=320;  pp=16;  ofs_row=5;  }
        else if (t < 5440){ base=1344; pp=64;  ofs_row=21; }
        else              { base=5440; pp=256; ofs_row=85; }
        int r = t - base;
        int bb = r / pp, p = r % pp;
        // harness compares idx as float VALUES -> write converted floats
        out[TOT + 1 + bb*ROWLEN + ofs_row + p] = (float)g_idx[t];
    }
}

extern "C" void kernel_launch(void* const* d_in, const int* in_sizes, int n_in,
                              void* d_out, int out_size){
    // Bind inputs by element count: z=524288, emb=131072, phi_w=36864, phi_b=128 (all distinct).
    const float* z = 0; const float* emb = 0; const float* phi_w = 0; const float* phi_b = 0;
    for (int i = 0; i < n_in; i++){
        switch (in_sizes[i]){
            case 524288: z     = (const float*)d_in[i]; break;
            case 131072: emb   = (const float*)d_in[i]; break;
            case 36864:  phi_w = (const float*)d_in[i]; break;
            case 128:    phi_b = (const float*)d_in[i]; break;
            default: break;
        }
    }
    float* out = (float*)d_out;
    (void)out_size;

    setup_kernel<<<(TOT + 255)/256, 256>>>(z, emb);

    // Replicate numpy: ticks = np.linspace(1/12, 1-1/12, 4) with linspace's exact
    // op sequence (step = delta/div; y_i = i*step + start; y[-1] = stop), then
    // pi = argmin |ticks - si/4| with strict-< first-wins tie-break.
    double start = 1.0/12.0;
    double stop  = 1.0 - 1.0/12.0;
    double step  = (stop - start) / 3.0;
    double ticks[4];
    for (int i = 0; i < 4; i++) ticks[i] = (double)i * step + start;
    ticks[3] = stop;
    int pis[5];
    for (int si = 0; si < 5; si++){
        double target = (double)si / 4.0;
        int bestp = 0; double bestd = fabs(ticks[0] - target);
        for (int p = 1; p < 4; p++){
            double d = fabs(ticks[p] - target);
            if (d < bestd){ bestd = d; bestp = p; }
        }
        pis[si] = bestp;
    }

    const int scales[5] = {1, 2, 4, 8, 16};
    const int splits[5] = {32, 32, 16, 8, 4};
    const int iofs[5]   = {0, 64, 320, 1344, 5440};

    for (int si = 0; si < 5; si++){
        int ph = scales[si];
        int N  = B*ph*ph;
        pool_kernel<<<(N*C + 255)/256, 256>>>(ph);
        dim3 g((N + 127)/128, splits[si]);
        argmin_kernel<<<g, 128>>>(emb, N, NE/splits[si]);
        gather_kernel<<<(TOT + 255)/256, 256>>>(emb, si, ph, iofs[si]);
        conv_update_kernel<<<dim3(B, 4), 128>>>(z, phi_w + pis[si]*C*C*9, phi_b + pis[si]*C, si);
    }
    pack_kernel<<<(TOT + 255)/256, 256>>>(z, out);
}

// round 6
// speedup vs baseline: 1.0900x; 1.0900x over previous
#include <cuda_runtime.h>
#include <cmath>

#define B 64
#define C 32
#define HW 16
#define IMG (C*HW*HW)        // 8192
#define TOT (B*IMG)          // 524288
#define NE 4096
#define NIDX 21824
#define ROWLEN 341
#define TCODES 128

// ---------------- scratch (no allocations allowed) ----------------
__device__ float g_zres[TOT];
__device__ float g_zhat[TOT];
__device__ float g_r[TOT];            // max N*C = 16384*32
__device__ float g_qup[TOT];
__device__ float g_hesq[NE];          // 0.5*||e||^2
__device__ unsigned long long g_res64[16384];
__device__ int   g_idx[NIDX];
__device__ float g_losspart[5*256];
__device__ int   g_itab[4][16][4];
__device__ float g_wtab[4][16][4];

// ---------------- helpers ----------------
__device__ __forceinline__ float cubicw(float x){
    const float A = -0.75f;
    x = fabsf(x);
    if (x <= 1.f) return ((A + 2.f)*x - (A + 3.f))*x*x + 1.f;
    if (x < 2.f)  return A*(((x - 5.f)*x + 8.f)*x - 4.f);
    return 0.f;
}
__device__ __forceinline__ void ffma2(unsigned long long &d, unsigned long long a, unsigned long long b){
    asm("fma.rn.f32x2 %0, %1, %2, %0;" : "+l"(d) : "l"(a), "l"(b));
}
__device__ __forceinline__ unsigned long long pk2(float a, float b){
    return ((unsigned long long)__float_as_uint(b) << 32) | (unsigned long long)__float_as_uint(a);
}
__device__ __forceinline__ float lo2(unsigned long long v){ return __uint_as_float((unsigned)v); }
__device__ __forceinline__ float hi2(unsigned long long v){ return __uint_as_float((unsigned)(v >> 32)); }
// order-preserving float -> uint map
__device__ __forceinline__ unsigned ford(float f){
    unsigned u = __float_as_uint(f);
    return (u & 0x80000000u) ? ~u : (u | 0x80000000u);
}

// ---------------- setup: copy z_res, zero z_hat, 0.5||e||^2, bicubic tables ----------------
__global__ void setup_kernel(const float* __restrict__ z, const float* __restrict__ emb){
    int t = blockIdx.x*blockDim.x + threadIdx.x;
    if (t < TOT){ g_zres[t] = z[t]; g_zhat[t] = 0.f; }
    if (t < NE){
        float s = 0.f;
        #pragma unroll
        for (int k = 0; k < C; k++){ float e = emb[t*C + k]; s += e*e; }
        g_hesq[t] = 0.5f*s;
    }
    if (t < 256){
        int s = t >> 6, rem = t & 63, Y = rem >> 2, a = rem & 3;
        int ph = 1 << s;
        float scale = (float)ph / 16.f;
        float src = ((float)Y + 0.5f)*scale - 0.5f;
        float i0 = floorf(src);
        float fr = src - i0;
        int off = a - 1;
        int idx = (int)i0 + off;
        idx = min(max(idx, 0), ph - 1);
        g_itab[s][Y][a] = idx;
        g_wtab[s][Y][a] = cubicw(fr - (float)off);
    }
}

// ---------------- area pool to [N][C] channel-last ----------------
__global__ void pool_kernel(int ph){
    int t = blockIdx.x*blockDim.x + threadIdx.x;
    int N = B*ph*ph;
    if (t >= N*C) return;
    int n = t >> 5, c = t & 31;
    int pp = ph*ph;
    int b = n / pp, rem = n % pp, y = rem / ph, x = rem % ph;
    int f = HW / ph;
    const float* base = g_zres + ((b*C + c)*HW + y*f)*HW + x*f;
    float s = 0.f;
    for (int dy = 0; dy < f; dy++)
        for (int dx = 0; dx < f; dx++)
            s += base[dy*HW + dx];
    g_r[n*C + c] = s * (1.f / (float)(f*f));
    if (c == 0) g_res64[n] = 0xFFFFFFFFFFFFFFFFull;
}

// ---------------- code search: score = 0.5||e||^2 - r.e, FFMA2 packed (2 MACs/issue) ----------------
__global__ __launch_bounds__(128) void argmin_kernel(const float* __restrict__ emb, int N, int chunk){
    __shared__ __align__(16) float et[C*TCODES];   // transposed [dim][code]
    __shared__ __align__(16) float hs[TCODES];
    int tid = threadIdx.x;
    int row = blockIdx.x*128 + tid;
    int cbase = blockIdx.y * chunk;
    bool active = row < N;

    unsigned long long nrp[C];       // packed {-r_d, -r_d}
    if (active){
        const float4* rp = (const float4*)(g_r + row*C);
        #pragma unroll
        for (int k = 0; k < 8; k++){
            float4 v = rp[k];
            nrp[4*k+0] = pk2(-v.x, -v.x);
            nrp[4*k+1] = pk2(-v.y, -v.y);
            nrp[4*k+2] = pk2(-v.z, -v.z);
            nrp[4*k+3] = pk2(-v.w, -v.w);
        }
    }
    float best = 3.4e38f; int bcode = 0;

    for (int tb = 0; tb < chunk; tb += TCODES){
        int code = cbase + tb + tid;
        const float4* src = (const float4*)(emb + code*C);
        __syncthreads();   // prior tile fully consumed
        #pragma unroll
        for (int k = 0; k < 8; k++){
            float4 v = src[k];
            et[(4*k+0)*TCODES + tid] = v.x;
            et[(4*k+1)*TCODES + tid] = v.y;
            et[(4*k+2)*TCODES + tid] = v.z;
            et[(4*k+3)*TCODES + tid] = v.w;
        }
        hs[tid] = g_hesq[code];
        __syncthreads();
        if (active){
            for (int jj = 0; jj < TCODES; jj += 8){
                const ulonglong2* h2 = (const ulonglong2*)(hs + jj);
                ulonglong2 ha = h2[0], hb = h2[1];
                unsigned long long a0 = ha.x, a1 = ha.y, a2 = hb.x, a3 = hb.y;
                #pragma unroll
                for (int d = 0; d < C; d++){
                    const ulonglong2* e2 = (const ulonglong2*)(et + d*TCODES + jj);
                    ulonglong2 ea = e2[0], eb = e2[1];
                    ffma2(a0, nrp[d], ea.x);
                    ffma2(a1, nrp[d], ea.y);
                    ffma2(a2, nrp[d], eb.x);
                    ffma2(a3, nrp[d], eb.y);
                }
                float s[8] = {lo2(a0),hi2(a0),lo2(a1),hi2(a1),lo2(a2),hi2(a2),lo2(a3),hi2(a3)};
                #pragma unroll
                for (int k = 0; k < 8; k++){
                    int cc = cbase + tb + jj + k;
                    if (s[k] < best){ best = s[k]; bcode = cc; }
                }
            }
        }
    }
    if (active){
        unsigned long long key = ((unsigned long long)ford(best) << 32) | (unsigned)bcode;
        atomicMin(&g_res64[row], key);
    }
}

// ---------------- gather + bicubic upsample to q_up [B][C][16][16], extract idx ----------------
__global__ void gather_kernel(const float* __restrict__ emb, int si, int ph, int idx_ofs){
    int t = blockIdx.x*blockDim.x + threadIdx.x;
    if (t >= TOT) return;
    int N = B*ph*ph;
    if (t < N) g_idx[idx_ofs + t] = (int)(g_res64[t] & 0xFFFFFFFFull);

    int x = t & 15, y = (t >> 4) & 15, c = (t >> 8) & 31, b = t >> 13;
    float out;
    if (si == 4){
        int n = (b*16 + y)*16 + x;
        int code = (int)(g_res64[n] & 0xFFFFFFFFull);
        out = emb[code*C + c];
    } else {
        int pp = ph*ph;
        float acc = 0.f;
        #pragma unroll
        for (int ax = 0; ax < 4; ax++){
            int   ix = g_itab[si][x][ax];
            float wx = g_wtab[si][x][ax];
            float sy = 0.f;
            #pragma unroll
            for (int ay = 0; ay < 4; ay++){
                int   iy = g_itab[si][y][ay];
                float wy = g_wtab[si][y][ay];
                int n = b*pp + iy*ph + ix;
                int code = (int)(g_res64[n] & 0xFFFFFFFFull);
                sy += wy * emb[code*C + c];
            }
            acc += wx * sy;
        }
        out = acc;
    }
    g_qup[t] = out;
}

// ---------------- Phi conv3x3 + residual update + loss partials ----------------
__global__ __launch_bounds__(128) void conv_update_kernel(const float* __restrict__ z,
        const float* __restrict__ w, const float* __restrict__ bias, int si){
    __shared__ float s_in[C][HW][HW];   // 32 KB
    __shared__ float s_w[8*C*9];        // 9 KB
    __shared__ float red[128];
    int b = blockIdx.x, og = blockIdx.y, t = threadIdx.x;

    const float4* gsrc = (const float4*)(g_qup + b*IMG);
    float4* sdst = (float4*)&s_in[0][0][0];
    for (int i = t; i < IMG/4; i += 128) sdst[i] = gsrc[i];
    for (int i = t; i < 8*C*9; i += 128) s_w[i] = w[og*8*C*9 + i];
    __syncthreads();

    int oc_l = t >> 4;   // 0..7
    int x    = t & 15;   // lanes vary over x -> conflict-free SMEM
    float acc[HW];
    #pragma unroll
    for (int y = 0; y < HW; y++) acc[y] = 0.f;

    for (int ci = 0; ci < C; ci++){
        #pragma unroll
        for (int kx = 0; kx < 3; kx++){
            int xx = x + kx - 1;
            if (xx < 0 || xx >= HW) continue;   // zero pad
            float w0 = s_w[(oc_l*C + ci)*9 + 0*3 + kx];
            float w1 = s_w[(oc_l*C + ci)*9 + 1*3 + kx];
            float w2 = s_w[(oc_l*C + ci)*9 + 2*3 + kx];
            #pragma unroll
            for (int yy = 0; yy < HW; yy++){
                float v = s_in[ci][yy][xx];
                if (yy >= 1)      acc[yy-1] += w2 * v;  // ky=2 -> y = yy-1
                acc[yy] += w1 * v;                      // ky=1 -> y = yy
                if (yy+1 < HW)    acc[yy+1] += w0 * v;  // ky=0 -> y = yy+1
            }
        }
    }

    int oc = og*8 + oc_l;
    float bval = bias[oc];
    float ls = 0.f;
    int gbase = ((b*C + oc)*HW)*HW + x;
    #pragma unroll
    for (int y = 0; y < HW; y++){
        float qv = 0.5f*s_in[oc][y][x] + 0.5f*(acc[y] + bval);
        int g = gbase + y*HW;
        float zh = g_zhat[g] + qv;
        g_zhat[g] = zh;
        g_zres[g] -= qv;
        float d = zh - z[g];
        ls += d*d;
    }
    red[t] = ls;
    __syncthreads();
    for (int s = 64; s > 0; s >>= 1){
        if (t < s) red[t] += red[t+s];
        __syncthreads();
    }
    if (t == 0) g_losspart[si*256 + b*4 + og] = red[0];
}

// ---------------- final pack: z_hat_st, loss, idx (as float values, batch-major scale blocks) ----------------
__global__ void pack_kernel(const float* __restrict__ z, float* __restrict__ out){
    int t = blockIdx.x*blockDim.x + threadIdx.x;
    if (t < TOT) out[t] = (g_zhat[t] - z[t]) + z[t];   // straight-through: value == z_hat
    if (t == 0){
        float s = 0.f;
        for (int i = 0; i < 5*256; i++) s += g_losspart[i];
        out[TOT] = s * (1.25f / ((float)TOT * 5.f));
    }
    if (t < NIDX){
        int base, pp, ofs_row;
        if      (t <   64){ base=0;    pp=1;   ofs_row=0;  }
        else if (t <  320){ base=64;   pp=4;   ofs_row=1;  }
        else if (t < 1344){ base=320;  pp=16;  ofs_row=5;  }
        else if (t < 5440){ base=1344; pp=64;  ofs_row=21; }
        else              { base=5440; pp=256; ofs_row=85; }
        int r = t - base;
        int bb = r / pp, p = r % pp;
        // harness compares idx as float VALUES -> write converted floats
        out[TOT + 1 + bb*ROWLEN + ofs_row + p] = (float)g_idx[t];
    }
}

extern "C" void kernel_launch(void* const* d_in, const int* in_sizes, int n_in,
                              void* d_out, int out_size){
    // Bind inputs by element count: z=524288, emb=131072, phi_w=36864, phi_b=128 (all distinct).
    const float* z = 0; const float* emb = 0; const float* phi_w = 0; const float* phi_b = 0;
    for (int i = 0; i < n_in; i++){
        switch (in_sizes[i]){
            case 524288: z     = (const float*)d_in[i]; break;
            case 131072: emb   = (const float*)d_in[i]; break;
            case 36864:  phi_w = (const float*)d_in[i]; break;
            case 128:    phi_b = (const float*)d_in[i]; break;
            default: break;
        }
    }
    float* out = (float*)d_out;
    (void)out_size;

    setup_kernel<<<(TOT + 255)/256, 256>>>(z, emb);

    // Replicate numpy: ticks = np.linspace(1/12, 1-1/12, 4) (exact op sequence),
    // pi = argmin |ticks - si/4| with strict-< first-wins tie-break.
    double start = 1.0/12.0;
    double stop  = 1.0 - 1.0/12.0;
    double step  = (stop - start) / 3.0;
    double ticks[4];
    for (int i = 0; i < 4; i++) ticks[i] = (double)i * step + start;
    ticks[3] = stop;
    int pis[5];
    for (int si = 0; si < 5; si++){
        double target = (double)si / 4.0;
        int bestp = 0; double bestd = fabs(ticks[0] - target);
        for (int p = 1; p < 4; p++){
            double d = fabs(ticks[p] - target);
            if (d < bestd){ bestd = d; bestp = p; }
        }
        pis[si] = bestp;
    }

    const int scales[5] = {1, 2, 4, 8, 16};
    const int splits[5] = {32, 32, 16, 8, 4};
    const int iofs[5]   = {0, 64, 320, 1344, 5440};

    for (int si = 0; si < 5; si++){
        int ph = scales[si];
        int N  = B*ph*ph;
        pool_kernel<<<(N*C + 255)/256, 256>>>(ph);
        dim3 g((N + 127)/128, splits[si]);
        argmin_kernel<<<g, 128>>>(emb, N, NE/splits[si]);
        gather_kernel<<<(TOT + 255)/256, 256>>>(emb, si, ph, iofs[si]);
        conv_update_kernel<<<dim3(B, 4), 128>>>(z, phi_w + pis[si]*C*C*9, phi_b + pis[si]*C, si);
    }
    pack_kernel<<<(TOT + 255)/256, 256>>>(z, out);
}